// round 3
// baseline (speedup 1.0000x reference)
#include <cuda_runtime.h>

// ButterflyRotationLayer: R = B(d,d) @ B(d,d/2) @ ... @ B(d,2), d=4096, 12 stages.
//
// Factorization: split the 12-stage product at k=64.
//   H = stages k=4096..128  -> H[r,l] != 0 only when l == r (mod 64)  (64 nnz/row)
//   T = stages k=64..2      -> block-diagonal with 64x64 blocks
// For output (r,c) exactly one l contributes:
//   l = (c>>6)*64 + (r&63)
//   R[r,c] = H[r,l] * T[l, c&63]
// H and T are 1 MB each; the final kernel is a write-bound outer product.

#define D 4096

// H stored as g_H[r*64 + m] = H[r, (r&63) + 64*m]
__device__ float g_H[D * 64];
// T stored as g_T[l*64 + cc] = T[l, (l>>6)*64 + cc]   (l = B*64 + rr)
__device__ float g_T[D * 64];

// ---------------------------------------------------------------------------
// Head: stages i = 0..5 (k = 4096 >> i), applied to e_r, tracked on the
// 64-element support {l : l == r (mod 64)}. In m-space (l = r6 + 64*m) the
// stages form a standard size-64 butterfly.
// ---------------------------------------------------------------------------
__global__ void butterfly_head_kernel(const float* __restrict__ thetas) {
    __shared__ float v[64];
    const int r   = blockIdx.x;
    const int tid = threadIdx.x;
    const int r6  = r & 63;

    v[tid] = (tid == (r >> 6)) ? 1.0f : 0.0f;
    __syncthreads();

#pragma unroll
    for (int i = 0; i < 6; ++i) {
        if (tid < 32) {
            const int half_m = 32 >> i;              // half in m-space
            const int bm   = tid >> (5 - i);         // pair -> m-block
            const int jm   = tid & (half_m - 1);
            const int m_p  = (bm << (6 - i)) + jm;
            const int m_q  = m_p + half_m;
            const int p    = r6 + (m_p << 6);        // full-space p index
            const int logk = 12 - i;                 // k = 2^logk
            const int half = 2048 >> i;
            const int t    = (p >> logk) * half + (p & ((1 << logk) - 1));
            float s, c;
            sincosf(thetas[i * 2048 + t], &s, &c);
            const float a = v[m_p], b = v[m_q];
            // row-vector update: v' = v @ B
            v[m_p] = c * a + s * b;
            v[m_q] = c * b - s * a;
        }
        __syncthreads();
    }
    g_H[(r << 6) + tid] = v[tid];
}

// ---------------------------------------------------------------------------
// Tail: stages i = 6..11 (k = 64 >> (i-6)), block-diagonal with 64x64 blocks.
// One launch-block per (64-block B, row-in-block rr): row l = B*64+rr of T.
// ---------------------------------------------------------------------------
__global__ void butterfly_tail_kernel(const float* __restrict__ thetas) {
    __shared__ float v[64];
    const int bid = blockIdx.x;     // = l = B*64 + rr
    const int B   = bid >> 6;
    const int rr  = bid & 63;
    const int tid = threadIdx.x;

    v[tid] = (tid == rr) ? 1.0f : 0.0f;
    __syncthreads();

#pragma unroll
    for (int ii = 0; ii < 6; ++ii) {
        const int i = ii + 6;                        // global stage index
        if (tid < 32) {
            const int half_l = 32 >> ii;             // local half within 64
            const int bm    = tid >> (5 - ii);
            const int jm    = tid & (half_l - 1);
            const int p_loc = (bm << (6 - ii)) + jm;
            const int q_loc = p_loc + half_l;
            const int p     = (B << 6) + p_loc;      // global index
            const int logk  = 12 - i;                // 6..1
            const int half  = 2048 >> i;
            const int t     = (p >> logk) * half + (p & ((1 << logk) - 1));
            float s, c;
            sincosf(thetas[i * 2048 + t], &s, &c);
            const float a = v[p_loc], b = v[q_loc];
            v[p_loc] = c * a + s * b;
            v[q_loc] = c * b - s * a;
        }
        __syncthreads();
    }
    g_T[(bid << 6) + tid] = v[tid];
}

// ---------------------------------------------------------------------------
// Final: R[r,c] = H[r, c>>6] * T[(c>>6)*64 + (r&63)][c&63]
// One float4 (4 consecutive c) per thread. Write-bound: 64 MB coalesced STG.128,
// 2 MB of L2-resident reads.
// ---------------------------------------------------------------------------
__global__ void outer_product_kernel(float4* __restrict__ out) {
    const int idx = blockIdx.x * blockDim.x + threadIdx.x;  // 0 .. 4M-1
    const int r   = idx >> 10;          // row (1024 float4 per row)
    const int c4  = idx & 1023;
    const int c   = c4 << 2;
    const int B   = c >> 6;

    const float  h = g_H[(r << 6) + B];
    const int    l = (B << 6) + (r & 63);
    const float4 t = *reinterpret_cast<const float4*>(&g_T[(l << 6) + (c & 63)]);

    out[idx] = make_float4(h * t.x, h * t.y, h * t.z, h * t.w);
}

extern "C" void kernel_launch(void* const* d_in, const int* in_sizes, int n_in,
                              void* d_out, int out_size) {
    const float* thetas = (const float*)d_in[0];  // [12, 2048] fp32
    float4* out = (float4*)d_out;                 // [4096, 4096] fp32

    butterfly_head_kernel<<<D, 64>>>(thetas);
    butterfly_tail_kernel<<<D, 64>>>(thetas);
    outer_product_kernel<<<(D * (D / 4)) / 256, 256>>>(out);
}

// round 4
// speedup vs baseline: 1.2820x; 1.2820x over previous
#include <cuda_runtime.h>

// ButterflyRotationLayer: R = B(d,d) @ B(d,d/2) @ ... @ B(d,2), d=4096, 12 stages.
//
// Split at k=64:
//   H = stages k=4096..128 : H[r,l] != 0 only when l == r (mod 64).
//       For fixed r6 = r&63, the 64 rows {r6+64*rh} share ONE 64x64 m-space
//       butterfly matrix Hhat_{r6}[rh, m]  (theta indices depend only on r6).
//   T = stages k=64..2     : block-diagonal, 64 independent 64x64 matrices
//       That_B[rr, cc].
// Exactly one l contributes per output element:
//   R[r6+64*rh, 64*B+cc] = Hhat_{r6}[rh, B] * That_B[r6, cc]
//
// Kernel 1: 128 blocks (64 head + 64 tail), each builds its 64x64 matrix in
//           smem via column Givens rotations; each theta's sincos computed once.
// Kernel 2: write-bound outer product, 64 MB coalesced float4 stores.

#define D 4096

// g_H[r*64 + m]  = Hhat_{r&63}[r>>6, m]   (= H[r, (r&63) + 64*m])
__device__ float g_H[D * 64];
// g_T[(B*64+rr)*64 + cc] = That_B[rr, cc] (= T[B*64+rr, B*64+cc])
__device__ float g_T[D * 64];

// ---------------------------------------------------------------------------
// Build all 128 small matrices. Block b in [0,64): head matrix for r6=b.
// Block b in [64,128): tail matrix for B=b-64.
// M = I; for each stage: M <- M @ B_i  (column rotations:
//   col_p' = c*col_p + s*col_q ; col_q' = c*col_q - s*col_p).
// The local pairing geometry is identical for head (m-space) and tail
// (within-block space); only the theta index differs.
// ---------------------------------------------------------------------------
__global__ __launch_bounds__(256) void butterfly_mats_kernel(const float* __restrict__ thetas) {
    __shared__ float sm[64][65];          // pad 65 -> conflict-free column access
    __shared__ float cs_c[32], cs_s[32];

    const int tid     = threadIdx.x;
    const int b       = blockIdx.x;
    const bool is_head = (b < 64);

    // identity
#pragma unroll
    for (int k = 0; k < 16; ++k) {
        const int e = tid + k * 256;
        sm[e >> 6][e & 63] = ((e >> 6) == (e & 63)) ? 1.0f : 0.0f;
    }
    __syncthreads();

    const int j = tid & 31;   // column-pair id, fixed per thread

#pragma unroll
    for (int ii = 0; ii < 6; ++ii) {
        const int half  = 32 >> ii;                  // local half
        const int bm    = j >> (5 - ii);
        const int jm    = j & (half - 1);
        const int p_loc = (bm << (6 - ii)) + jm;
        const int q_loc = p_loc + half;

        if (tid < 32) {
            int theta_idx;
            if (is_head) {
                // global index p = r6 + m_p*64, stage i = ii (k = 4096>>ii)
                const int p    = b + (p_loc << 6);
                const int logk = 12 - ii;
                const int hh   = 2048 >> ii;
                theta_idx = ii * 2048 + (p >> logk) * hh + (p & ((1 << logk) - 1));
            } else {
                // global index p = B*64 + p_loc, stage i = ii+6 (k = 64>>ii)
                const int p    = ((b - 64) << 6) + p_loc;
                const int logk = 6 - ii;
                const int hh   = 32 >> ii;
                theta_idx = (ii + 6) * 2048 + (p >> logk) * hh + (p & ((1 << logk) - 1));
            }
            float s, c;
            sincosf(thetas[theta_idx], &s, &c);
            cs_c[tid] = c;
            cs_s[tid] = s;
        }
        __syncthreads();

        const float c = cs_c[j];
        const float s = cs_s[j];
#pragma unroll
        for (int k = 0; k < 8; ++k) {
            const int row = (tid >> 5) + (k << 3);   // 8 rows per thread
            const float a  = sm[row][p_loc];
            const float bb = sm[row][q_loc];
            sm[row][p_loc] = c * a + s * bb;
            sm[row][q_loc] = c * bb - s * a;
        }
        __syncthreads();
    }

    if (is_head) {
        // g_H[(r6 + 64*rh)*64 + m] = sm[rh][m]
#pragma unroll
        for (int k = 0; k < 16; ++k) {
            const int e  = tid + k * 256;
            const int rh = e >> 6;
            const int m  = e & 63;
            g_H[(b << 6) + (rh << 12) + m] = sm[rh][m];
        }
    } else {
        // g_T[(B*64+rr)*64 + cc] contiguous 16 KB block
        const int base = (b - 64) << 12;
#pragma unroll
        for (int k = 0; k < 16; ++k) {
            const int e = tid + k * 256;
            g_T[base + e] = sm[e >> 6][e & 63];
        }
    }
}

// ---------------------------------------------------------------------------
// R[r, c] = g_H[r*64 + (c>>6)] * g_T[((c>>6)*64 + (r&63))*64 + (c&63)]
// One block per output row; 4 coalesced float4 stores per thread.
// ---------------------------------------------------------------------------
__global__ __launch_bounds__(256) void outer_product_kernel(float4* __restrict__ out) {
    const int r   = blockIdx.x;
    const int tid = threadIdx.x;
    const int r6  = r & 63;
    const float* __restrict__ Hrow = &g_H[r << 6];
    float4* __restrict__ orow = out + ((long)r << 10);   // 1024 float4 per row

#pragma unroll
    for (int k = 0; k < 4; ++k) {
        const int c4 = tid + (k << 8);       // float4 index within row
        const int c  = c4 << 2;
        const int B  = c >> 6;
        const float h = Hrow[B];
        const int l   = (B << 6) + r6;
        const float4 t = *reinterpret_cast<const float4*>(&g_T[(l << 6) + (c & 63)]);
        orow[c4] = make_float4(h * t.x, h * t.y, h * t.z, h * t.w);
    }
}

extern "C" void kernel_launch(void* const* d_in, const int* in_sizes, int n_in,
                              void* d_out, int out_size) {
    const float* thetas = (const float*)d_in[0];  // [12, 2048] fp32
    float4* out = (float4*)d_out;                 // [4096, 4096] fp32

    butterfly_mats_kernel<<<128, 256>>>(thetas);
    outer_product_kernel<<<D, 256>>>(out);
}

// round 5
// speedup vs baseline: 1.2859x; 1.0031x over previous
#include <cuda_runtime.h>

// ButterflyRotationLayer: R = B(d,d) @ B(d,d/2) @ ... @ B(d,2), d=4096, 12 stages.
//
// Split at k=64:
//   H = stages k=4096..128 : H[r,l] != 0 only when l == r (mod 64).
//       For fixed r6 = r&63, the 64 rows {r6+64*rh} share ONE 64x64 m-space
//       butterfly matrix Hhat_{r6}[rh, m].
//   T = stages k=64..2     : block-diagonal, 64 independent 64x64 matrices That_B.
// Exactly one l contributes per output element:
//   R[r6+64*rh, 64*B+cc] = Hhat_{r6}[rh, B] * That_B[r6, cc]
//
// Kernel 1: builds all 128 small 64x64 matrices (sincos once per theta).
// Kernel 2: outer product; T-slice for the block's shared r6 staged in SMEM so
//           L2 only sees the 64 MB of output stores (+ ~9 MB of reads).

#define D 4096

// g_H[r*64 + m]  = Hhat_{r&63}[r>>6, m]
__device__ __align__(16) float g_H[D * 64];
// g_T[(B*64+rr)*64 + cc] = That_B[rr, cc]
__device__ __align__(16) float g_T[D * 64];

// ---------------------------------------------------------------------------
// Kernel 1: block b<64 -> head matrix Hhat_{r6=b}; b>=64 -> tail matrix That_{b-64}.
// M = I; each stage applies column Givens rotations (M <- M @ B_i).
// ---------------------------------------------------------------------------
__global__ __launch_bounds__(256) void butterfly_mats_kernel(const float* __restrict__ thetas) {
    __shared__ float sm[64][65];
    __shared__ float cs_c[32], cs_s[32];

    const int tid      = threadIdx.x;
    const int b        = blockIdx.x;
    const bool is_head = (b < 64);

#pragma unroll
    for (int k = 0; k < 16; ++k) {
        const int e = tid + k * 256;
        sm[e >> 6][e & 63] = ((e >> 6) == (e & 63)) ? 1.0f : 0.0f;
    }
    __syncthreads();

    const int j = tid & 31;

#pragma unroll
    for (int ii = 0; ii < 6; ++ii) {
        const int half  = 32 >> ii;
        const int bm    = j >> (5 - ii);
        const int jm    = j & (half - 1);
        const int p_loc = (bm << (6 - ii)) + jm;
        const int q_loc = p_loc + half;

        if (tid < 32) {
            int theta_idx;
            if (is_head) {
                const int p    = b + (p_loc << 6);
                const int logk = 12 - ii;
                const int hh   = 2048 >> ii;
                theta_idx = ii * 2048 + (p >> logk) * hh + (p & ((1 << logk) - 1));
            } else {
                const int p    = ((b - 64) << 6) + p_loc;
                const int logk = 6 - ii;
                const int hh   = 32 >> ii;
                theta_idx = (ii + 6) * 2048 + (p >> logk) * hh + (p & ((1 << logk) - 1));
            }
            float s, c;
            sincosf(thetas[theta_idx], &s, &c);
            cs_c[tid] = c;
            cs_s[tid] = s;
        }
        __syncthreads();

        const float c = cs_c[j];
        const float s = cs_s[j];
#pragma unroll
        for (int k = 0; k < 8; ++k) {
            const int row = (tid >> 5) + (k << 3);
            const float a  = sm[row][p_loc];
            const float bb = sm[row][q_loc];
            sm[row][p_loc] = c * a + s * bb;
            sm[row][q_loc] = c * bb - s * a;
        }
        __syncthreads();
    }

    if (is_head) {
#pragma unroll
        for (int k = 0; k < 16; ++k) {
            const int e  = tid + k * 256;
            const int rh = e >> 6;
            const int m  = e & 63;
            g_H[(b << 6) + (rh << 12) + m] = sm[rh][m];
        }
    } else {
        const int base = (b - 64) << 12;
#pragma unroll
        for (int k = 0; k < 16; ++k) {
            const int e = tid + k * 256;
            g_T[base + e] = sm[e >> 6][e & 63];
        }
    }
}

// ---------------------------------------------------------------------------
// Kernel 2: grid = 64 r6-groups x 8 sub-blocks. Block (r6, grp) handles the 8
// rows r = r6 + 64*(grp*8 + jrow). T-slice T_sh[B][cc] = That_B[r6, cc] (16 KB)
// and H values H_sh[jrow][B] (2 KB) staged in SMEM; 32 coalesced float4 stores
// per thread.
// ---------------------------------------------------------------------------
__global__ __launch_bounds__(256) void outer_product_kernel(float4* __restrict__ out) {
    __shared__ float T_sh[64][64];   // [B][cc]
    __shared__ float H_sh[8][64];    // [jrow][B]

    const int tid = threadIdx.x;
    const int r6  = blockIdx.x >> 3;
    const int grp = blockIdx.x & 7;

    // Stage T-slice: T_sh[B][cc] = g_T[((B<<6)+r6)<<6 + cc]
#pragma unroll
    for (int k = 0; k < 4; ++k) {
        const int e4  = tid + (k << 8);         // float4 index 0..1023
        const int B   = e4 >> 4;
        const int cc4 = e4 & 15;
        const float4 v = *reinterpret_cast<const float4*>(
            &g_T[(((B << 6) + r6) << 6) + (cc4 << 2)]);
        *reinterpret_cast<float4*>(&T_sh[B][cc4 << 2]) = v;
    }
    // Stage H values: rows r = r6 + 64*(grp*8 + jrow)
#pragma unroll
    for (int k = 0; k < 2; ++k) {
        const int e = tid + (k << 8);           // 0..511
        const int jrow = e >> 6;
        const int B    = e & 63;
        const int r    = r6 + ((grp << 3) + jrow) * 64;
        H_sh[jrow][B] = g_H[(r << 6) + B];
    }
    __syncthreads();

#pragma unroll
    for (int jrow = 0; jrow < 8; ++jrow) {
        const int r = r6 + (((grp << 3) + jrow) << 6);
        float4* __restrict__ orow = out + ((long)r << 10);
#pragma unroll
        for (int k = 0; k < 4; ++k) {
            const int c4  = tid + (k << 8);
            const int B   = c4 >> 4;
            const int cc4 = c4 & 15;
            const float h = H_sh[jrow][B];
            const float4 t = *reinterpret_cast<const float4*>(&T_sh[B][cc4 << 2]);
            orow[c4] = make_float4(h * t.x, h * t.y, h * t.z, h * t.w);
        }
    }
}

extern "C" void kernel_launch(void* const* d_in, const int* in_sizes, int n_in,
                              void* d_out, int out_size) {
    const float* thetas = (const float*)d_in[0];  // [12, 2048] fp32
    float4* out = (float4*)d_out;                 // [4096, 4096] fp32

    butterfly_mats_kernel<<<128, 256>>>(thetas);
    outer_product_kernel<<<512, 256>>>(out);
}